// round 13
// baseline (speedup 1.0000x reference)
#include <cuda_runtime.h>
#include <cuda_bf16.h>
#include <math.h>
#include <stdint.h>

#define NCAM 6
#define QTOT 1024
#define KTOT 1680

__device__ __nv_bfloat16 g_Qbf[8 * NCAM * QTOT * 32];
__device__ __nv_bfloat16 g_Kbf[8 * NCAM * KTOT * 32];
__device__ __nv_bfloat16 g_Vt [8 * NCAM * 32 * KTOT + 64];
__device__ __nv_bfloat16 g_Wt [3 * 128 * 128];
__device__ __nv_bfloat16 g_We [2 * 81920];  // hi plane | lo plane (Wp^T|W1^T|W2^T)
__device__ float g_Op[48 * QTOT * 32];
__device__ float g_lp[48 * QTOT];

__device__ __forceinline__ void mma16816(float* d, const uint32_t* a,
                                         uint32_t b0, uint32_t b1, const float* c) {
    asm volatile("mma.sync.aligned.m16n8k16.row.col.f32.bf16.bf16.f32 "
        "{%0,%1,%2,%3}, {%4,%5,%6,%7}, {%8,%9}, {%10,%11,%12,%13};"
        : "=f"(d[0]), "=f"(d[1]), "=f"(d[2]), "=f"(d[3])
        : "r"(a[0]), "r"(a[1]), "r"(a[2]), "r"(a[3]), "r"(b0), "r"(b1),
          "f"(c[0]), "f"(c[1]), "f"(c[2]), "f"(c[3]));
}

__device__ __forceinline__ void bf16_split(float v, __nv_bfloat16& hi, __nv_bfloat16& lo) {
    hi = __float2bfloat16(v);
    lo = __float2bfloat16(v - __bfloat162float(hi));
}

// ===========================================================================
// Kernel 0: weights -> bf16. Proj: plain bf16 transposed. Epi: hi+lo planes.
// ===========================================================================
__global__ void prep_kernel(const float* __restrict__ Wq, const float* __restrict__ Wk,
                            const float* __restrict__ Wv, const float* __restrict__ Wp,
                            const float* __restrict__ W1, const float* __restrict__ W2)
{
    const int base = blockIdx.x * 1024;
    for (int i = base + threadIdx.x; i < base + 1024; i += 256) {
        if (i < 49152) {
            int sel = i >> 14, j = i & 16383;
            const float* W = (sel == 0) ? Wq : ((sel == 1) ? Wk : Wv);
            g_Wt[i] = __float2bfloat16(W[(j & 127) * 128 + (j >> 7)]);
        } else {
            int j = i - 49152;  // 0..81919
            float v;
            if (j < 16384)      v = Wp[(j & 127) * 128 + (j >> 7)];
            else if (j < 49152) { int jj = j - 16384; v = W1[(jj & 127) * 256 + (jj >> 7)]; }
            else                { int jj = j - 49152; v = W2[(jj & 255) * 128 + (jj >> 8)]; }
            __nv_bfloat16 hi, lo;
            bf16_split(v, hi, lo);
            g_We[j] = hi;
            g_We[81920 + j] = lo;
        }
    }
}

// ===========================================================================
// Kernel 1: fused Q/K/V projection (unchanged).
// ===========================================================================
__global__ __launch_bounds__(256) void proj_mma(
    const float* __restrict__ xq, const float* __restrict__ xk,
    const float* __restrict__ xv,
    const float* __restrict__ gq, const float* __restrict__ bq_ln,
    const float* __restrict__ gk, const float* __restrict__ bk_ln,
    const float* __restrict__ gv, const float* __restrict__ bv_ln,
    const float* __restrict__ biq, const float* __restrict__ bik,
    const float* __restrict__ biv)
{
    __shared__ __align__(16) unsigned char buf[43520];
    float (*XsF)[132] = (float(*)[132])buf;
    __nv_bfloat16* Wts = (__nv_bfloat16*)buf;
    __nv_bfloat16* Xbf = (__nv_bfloat16*)(buf + 34816);
    __nv_bfloat16* VS  = (__nv_bfloat16*)buf;

    const int z = blockIdx.z;
    const int sel = z >> 1, b = z & 1;
    const int npos = sel ? KTOT : QTOT;
    const int p0 = blockIdx.x * 32;
    if (p0 >= npos) return;

    const float* x   = (sel == 0) ? xq : ((sel == 1) ? xk : xv);
    const float* lng = (sel == 0) ? gq : ((sel == 1) ? gk : gv);
    const float* lnb = (sel == 0) ? bq_ln : ((sel == 1) ? bk_ln : bv_ln);
    const float* bias = (sel == 0) ? biq : ((sel == 1) ? bik : biv);

    const int tid = threadIdx.x, lane = tid & 31, wid = tid >> 5;
    const int n = blockIdx.y;
    const float* xb = x + (size_t)(b * NCAM + n) * 128 * npos;

    for (int i = tid; i < 4096; i += 256) {
        int tok = i & 31, d = i >> 5;
        int tg = min(p0 + tok, npos - 1);
        XsF[tok][d] = xb[(size_t)d * npos + tg];
    }
    __syncthreads();

    {
        const int token = tid >> 3, s = tid & 7;
        float sum = 0.f;
        #pragma unroll
        for (int t = 0; t < 16; t++) sum += XsF[token][s + 8 * t];
        sum += __shfl_xor_sync(~0u, sum, 1); sum += __shfl_xor_sync(~0u, sum, 2);
        sum += __shfl_xor_sync(~0u, sum, 4);
        const float mu = sum * (1.f / 128.f);
        float v = 0.f;
        #pragma unroll
        for (int t = 0; t < 16; t++) { float d = XsF[token][s + 8 * t] - mu; v += d * d; }
        v += __shfl_xor_sync(~0u, v, 1); v += __shfl_xor_sync(~0u, v, 2);
        v += __shfl_xor_sync(~0u, v, 4);
        const float rstd = rsqrtf(v * (1.f / 128.f) + 1e-5f);
        #pragma unroll
        for (int t = 0; t < 16; t++) {
            int d = s + 8 * t;
            Xbf[token * 136 + d] =
                __float2bfloat16((XsF[token][d] - mu) * rstd * lng[d] + lnb[d]);
        }
    }
    __syncthreads();

    {
        const __nv_bfloat16* Wg = g_Wt + sel * 16384;
        for (int u = tid; u < 2048; u += 256) {
            int nr = u >> 4, seg = u & 15;
            *(uint4*)(buf + nr * 272 + seg * 16) = *(const uint4*)(Wg + nr * 128 + seg * 8);
        }
    }
    __syncthreads();

    const int mt = wid & 1, nh = wid >> 1;
    const int r = lane >> 2, qn = (lane & 3) * 2;
    float c[4][4];
    #pragma unroll
    for (int nt = 0; nt < 4; nt++) {
        int cc = 32 * nh + 8 * nt + qn;
        c[nt][0] = c[nt][2] = bias[cc];
        c[nt][1] = c[nt][3] = bias[cc + 1];
    }
    #pragma unroll
    for (int ks = 0; ks < 8; ks++) {
        uint32_t a[4];
        a[0] = *(const uint32_t*)(Xbf + (16 * mt + r) * 136 + 16 * ks + qn);
        a[1] = *(const uint32_t*)(Xbf + (16 * mt + r + 8) * 136 + 16 * ks + qn);
        a[2] = *(const uint32_t*)(Xbf + (16 * mt + r) * 136 + 16 * ks + qn + 8);
        a[3] = *(const uint32_t*)(Xbf + (16 * mt + r + 8) * 136 + 16 * ks + qn + 8);
        #pragma unroll
        for (int nt = 0; nt < 4; nt++) {
            uint32_t b0 = *(const uint32_t*)(Wts + (32 * nh + 8 * nt + r) * 136 + 16 * ks + qn);
            uint32_t b1 = *(const uint32_t*)(Wts + (32 * nh + 8 * nt + r) * 136 + 16 * ks + qn + 8);
            mma16816(c[nt], a, b0, b1, c[nt]);
        }
    }

    if (sel == 2) {
        __syncthreads();
        #pragma unroll
        for (int nt = 0; nt < 4; nt++) {
            int cc = 32 * nh + 8 * nt + qn, tokr = 16 * mt + r;
            VS[cc * 40 + tokr]           = __float2bfloat16(c[nt][0]);
            VS[(cc + 1) * 40 + tokr]     = __float2bfloat16(c[nt][1]);
            VS[cc * 40 + tokr + 8]       = __float2bfloat16(c[nt][2]);
            VS[(cc + 1) * 40 + tokr + 8] = __float2bfloat16(c[nt][3]);
        }
        __syncthreads();
        for (int u = tid; u < 512; u += 256) {
            int row = u >> 2, seg = u & 3, k = p0 + seg * 8;
            if (k < npos) {
                size_t dst = ((size_t)((b * 4 + (row >> 5)) * NCAM + n) * 32 + (row & 31))
                             * (size_t)npos + k;
                *(uint4*)(g_Vt + dst) = *(const uint4*)(VS + row * 40 + seg * 8);
            }
        }
    } else {
        const float sc = sel ? 1.f : 0.17677669529663687f;
        __nv_bfloat16* op = sel ? g_Kbf : g_Qbf;
        const size_t rowb = ((size_t)(b * 4 + nh) * NCAM + n) * npos;
        const int t0 = p0 + 16 * mt + r, t1 = t0 + 8;
        #pragma unroll
        for (int nt = 0; nt < 4; nt++) {
            int ccl = 8 * nt + qn;
            if (t0 < npos)
                *(__nv_bfloat162*)(op + (rowb + t0) * 32 + ccl) =
                    __floats2bfloat162_rn(c[nt][0] * sc, c[nt][1] * sc);
            if (t1 < npos)
                *(__nv_bfloat162*)(op + (rowb + t1) * 32 + ccl) =
                    __floats2bfloat162_rn(c[nt][2] * sc, c[nt][3] * sc);
        }
    }
}

// ===========================================================================
// Kernel 2: mma.sync bf16 attention, per-camera split (unchanged).
// ===========================================================================
__global__ __launch_bounds__(256, 2) void attn_mma()
{
    __shared__ __nv_bfloat16 Qs[128][40];
    __shared__ __nv_bfloat16 Ks[2][64][40];
    __shared__ __nv_bfloat16 Vs[2][32][72];

    const int tid = threadIdx.x, wid = tid >> 5, lane = tid & 31;
    const int q0 = blockIdx.x * 128, bm = blockIdx.y, cam = blockIdx.z;

    const __nv_bfloat16* Qbase = g_Qbf + ((size_t)(bm * NCAM + cam) * QTOT + q0) * 32;
    const __nv_bfloat16* Kbase = g_Kbf + (size_t)(bm * NCAM + cam) * KTOT * 32;
    const __nv_bfloat16* Vbase = g_Vt + (size_t)(bm * NCAM + cam) * 32 * (size_t)KTOT;

    const int krow = tid >> 2, kseg = tid & 3;
    const int vrow = tid >> 3, vseg = tid & 7;

    #pragma unroll
    for (int h = 0; h < 2; h++) {
        int rr = (tid + h * 256) >> 2;
        *(uint4*)&Qs[rr][kseg * 8] = *(const uint4*)(Qbase + (size_t)rr * 32 + kseg * 8);
    }
    *(uint4*)&Ks[0][krow][kseg * 8] = *(const uint4*)(Kbase + (size_t)krow * 32 + kseg * 8);
    *(uint4*)&Vs[0][vrow][vseg * 8] = *(const uint4*)(Vbase + (size_t)vrow * KTOT + vseg * 8);
    __syncthreads();

    const int r = lane >> 2, qn = (lane & 3) * 2;
    uint32_t qa[2][4];
    #pragma unroll
    for (int ks = 0; ks < 2; ks++) {
        qa[ks][0] = *(const uint32_t*)&Qs[16 * wid + r][16 * ks + qn];
        qa[ks][1] = *(const uint32_t*)&Qs[16 * wid + r + 8][16 * ks + qn];
        qa[ks][2] = *(const uint32_t*)&Qs[16 * wid + r][16 * ks + qn + 8];
        qa[ks][3] = *(const uint32_t*)&Qs[16 * wid + r + 8][16 * ks + qn + 8];
    }

    float O[4][4];
    #pragma unroll
    for (int ct = 0; ct < 4; ct++)
        #pragma unroll
        for (int e = 0; e < 4; e++) O[ct][e] = 0.f;
    float l0 = 0.f, l1 = 0.f;

    #pragma unroll 1
    for (int t = 0; t < 27; t++) {
        const int buf = t & 1;
        const int kb = t * 64;

        uint4 kpf, vpf;
        if (t < 26) {
            const int kbn = (t + 1) * 64;
            int kr = min(kbn + krow, KTOT - 1);
            kpf = *(const uint4*)(Kbase + (size_t)kr * 32 + kseg * 8);
            if (kbn + vseg * 8 >= KTOT) vpf = make_uint4(0, 0, 0, 0);
            else vpf = *(const uint4*)(Vbase + (size_t)vrow * KTOT + kbn + vseg * 8);
        }

        float s[8][4];
        #pragma unroll
        for (int nt = 0; nt < 8; nt++) {
            s[nt][0] = s[nt][1] = s[nt][2] = s[nt][3] = 0.f;
            #pragma unroll
            for (int ks = 0; ks < 2; ks++) {
                uint32_t b0 = *(const uint32_t*)&Ks[buf][8 * nt + r][16 * ks + qn];
                uint32_t b1 = *(const uint32_t*)&Ks[buf][8 * nt + r][16 * ks + 8 + qn];
                mma16816(s[nt], qa[ks], b0, b1, s[nt]);
            }
        }

        const int nvalid = KTOT - kb;
        #pragma unroll
        for (int nt = 0; nt < 8; nt++) {
            const int c0 = 8 * nt + qn;
            #pragma unroll
            for (int e = 0; e < 4; e++) {
                float p = __expf(s[nt][e]);
                if (c0 + (e & 1) >= nvalid) p = 0.f;
                s[nt][e] = p;
            }
            l0 += s[nt][0] + s[nt][1];
            l1 += s[nt][2] + s[nt][3];
        }

        uint32_t pa[4][4];
        #pragma unroll
        for (int kk = 0; kk < 4; kk++) {
            __nv_bfloat162 t0 = __floats2bfloat162_rn(s[2 * kk][0], s[2 * kk][1]);
            __nv_bfloat162 t1 = __floats2bfloat162_rn(s[2 * kk][2], s[2 * kk][3]);
            __nv_bfloat162 t2 = __floats2bfloat162_rn(s[2 * kk + 1][0], s[2 * kk + 1][1]);
            __nv_bfloat162 t3 = __floats2bfloat162_rn(s[2 * kk + 1][2], s[2 * kk + 1][3]);
            pa[kk][0] = *(uint32_t*)&t0; pa[kk][1] = *(uint32_t*)&t1;
            pa[kk][2] = *(uint32_t*)&t2; pa[kk][3] = *(uint32_t*)&t3;
        }

        #pragma unroll
        for (int ct = 0; ct < 4; ct++) {
            #pragma unroll
            for (int kk = 0; kk < 4; kk++) {
                uint32_t b0 = *(const uint32_t*)&Vs[buf][8 * ct + r][16 * kk + qn];
                uint32_t b1 = *(const uint32_t*)&Vs[buf][8 * ct + r][16 * kk + 8 + qn];
                mma16816(O[ct], pa[kk], b0, b1, O[ct]);
            }
        }

        if (t < 26) {
            *(uint4*)&Ks[buf ^ 1][krow][kseg * 8] = kpf;
            *(uint4*)&Vs[buf ^ 1][vrow][vseg * 8] = vpf;
        }
        __syncthreads();
    }

    l0 += __shfl_xor_sync(~0u, l0, 1); l0 += __shfl_xor_sync(~0u, l0, 2);
    l1 += __shfl_xor_sync(~0u, l1, 1); l1 += __shfl_xor_sync(~0u, l1, 2);

    const int bmh = cam * 8 + bm;
    float* Od = g_Op + ((size_t)bmh * QTOT + q0 + 16 * wid + r) * 32;
    float* Od2 = Od + 8 * 32;
    #pragma unroll
    for (int ct = 0; ct < 4; ct++) {
        *(float2*)&Od[8 * ct + qn] = make_float2(O[ct][0], O[ct][1]);
        *(float2*)&Od2[8 * ct + qn] = make_float2(O[ct][2], O[ct][3]);
    }
    if ((lane & 3) == 0) {
        g_lp[bmh * QTOT + q0 + 16 * wid + r] = l0;
        g_lp[bmh * QTOT + q0 + 16 * wid + r + 8] = l1;
    }
}

// ===========================================================================
// Compensated HMMA GEMM: C += (Ah+Al) @ (Wh+Wl)^T, dropping Al@Wl.
// W staged in 32-k chunks (128 n x 32 k, hi+lo), next chunk reg-prefetched.
// Warp w owns output cols [16w, 16w+16).
// ===========================================================================
__device__ __forceinline__ void hgemm16c(
    const __nv_bfloat16* __restrict__ Whi, const __nv_bfloat16* __restrict__ Wlo,
    int kpitch, int n0, int kbase,
    const __nv_bfloat16* __restrict__ Ahi, const __nv_bfloat16* __restrict__ Alo,
    __nv_bfloat16* __restrict__ WsH, __nv_bfloat16* __restrict__ WsL,
    float* cA, float* cB, int w, int r, int qn, int tid)
{
    uint4 ph[2], pl[2];
    #pragma unroll
    for (int j = 0; j < 2; j++) {
        int f = tid + 256 * j, row = f >> 2, seg = f & 3;
        size_t off = (size_t)(n0 + row) * kpitch + kbase + seg * 8;
        ph[j] = *(const uint4*)(Whi + off);
        pl[j] = *(const uint4*)(Wlo + off);
    }
    #pragma unroll 1
    for (int ch = 0; ch < 4; ch++) {
        #pragma unroll
        for (int j = 0; j < 2; j++) {
            int f = tid + 256 * j, row = f >> 2, seg = f & 3;
            *(uint4*)&WsH[row * 40 + seg * 8] = ph[j];
            *(uint4*)&WsL[row * 40 + seg * 8] = pl[j];
        }
        __syncthreads();
        if (ch < 3) {
            #pragma unroll
            for (int j = 0; j < 2; j++) {
                int f = tid + 256 * j, row = f >> 2, seg = f & 3;
                size_t off = (size_t)(n0 + row) * kpitch + kbase + (ch + 1) * 32 + seg * 8;
                ph[j] = *(const uint4*)(Whi + off);
                pl[j] = *(const uint4*)(Wlo + off);
            }
        }
        #pragma unroll
        for (int ks = 0; ks < 2; ks++) {
            const int kk = ch * 32 + ks * 16, lk = ks * 16;
            uint32_t ah[4], al[4];
            ah[0] = *(const uint32_t*)&Ahi[r * 136 + kk + qn];
            ah[1] = *(const uint32_t*)&Ahi[(r + 8) * 136 + kk + qn];
            ah[2] = *(const uint32_t*)&Ahi[r * 136 + kk + 8 + qn];
            ah[3] = *(const uint32_t*)&Ahi[(r + 8) * 136 + kk + 8 + qn];
            al[0] = *(const uint32_t*)&Alo[r * 136 + kk + qn];
            al[1] = *(const uint32_t*)&Alo[(r + 8) * 136 + kk + qn];
            al[2] = *(const uint32_t*)&Alo[r * 136 + kk + 8 + qn];
            al[3] = *(const uint32_t*)&Alo[(r + 8) * 136 + kk + 8 + qn];
            {
                uint32_t bh0 = *(const uint32_t*)&WsH[(16 * w + r) * 40 + lk + qn];
                uint32_t bh1 = *(const uint32_t*)&WsH[(16 * w + r) * 40 + lk + 8 + qn];
                uint32_t bl0 = *(const uint32_t*)&WsL[(16 * w + r) * 40 + lk + qn];
                uint32_t bl1 = *(const uint32_t*)&WsL[(16 * w + r) * 40 + lk + 8 + qn];
                mma16816(cA, ah, bh0, bh1, cA);
                mma16816(cA, al, bh0, bh1, cA);
                mma16816(cA, ah, bl0, bl1, cA);
            }
            {
                uint32_t bh0 = *(const uint32_t*)&WsH[(16 * w + 8 + r) * 40 + lk + qn];
                uint32_t bh1 = *(const uint32_t*)&WsH[(16 * w + 8 + r) * 40 + lk + 8 + qn];
                uint32_t bl0 = *(const uint32_t*)&WsL[(16 * w + 8 + r) * 40 + lk + qn];
                uint32_t bl1 = *(const uint32_t*)&WsL[(16 * w + 8 + r) * 40 + lk + 8 + qn];
                mma16816(cB, ah, bh0, bh1, cB);
                mma16816(cB, al, bh0, bh1, cB);
                mma16816(cB, ah, bl0, bl1, cB);
            }
        }
        __syncthreads();
    }
}

// ===========================================================================
// Kernel 3: merge + Wp + skip + preLN + GELU MLP + postLN; compensated HMMA.
//   16 tokens/block, 128 blocks, 256 threads (8 warps x 16 cols each).
// ===========================================================================
__global__ __launch_bounds__(256) void epi_kernel(
    const float* __restrict__ skip, const float* __restrict__ bp,
    const float* __restrict__ pre_g, const float* __restrict__ pre_b,
    const float* __restrict__ b1, const float* __restrict__ b2,
    const float* __restrict__ post_g, const float* __restrict__ post_b,
    float* __restrict__ out)
{
    __shared__ __nv_bfloat16 WsH[128 * 40];    // 10240 B
    __shared__ __nv_bfloat16 WsL[128 * 40];    // 10240 B
    __shared__ __nv_bfloat16 AbfH[16 * 136], AbfL[16 * 136];   // 8704 B
    __shared__ __nv_bfloat16 HbfH[16 * 136], HbfL[16 * 136];   // 8704 B
    __shared__ float Zsf[16 * 132];            // 8448 B   (total 46336)

    const int tid = threadIdx.x, w = tid >> 5, lane = tid & 31;
    const int r = lane >> 2, qn = (lane & 3) * 2;
    const int tok0 = blockIdx.x * 16;
    const int b = tok0 >> 10, p0 = tok0 & 1023;

    // ---- merge 6-camera partials -> A (hi+lo) ----
    for (int i = tid; i < 512; i += 256) {
        int row = i >> 5, c4 = i & 31;
        int col0 = c4 * 4, m = col0 >> 5, c = col0 & 31;
        int qq = p0 + row, bmh = b * 4 + m;
        float l = 0.f, o4[4] = {0.f, 0.f, 0.f, 0.f};
        #pragma unroll
        for (int cm = 0; cm < 6; cm++) {
            int idx = cm * 8 + bmh;
            l += g_lp[idx * QTOT + qq];
            float4 o = *(const float4*)&g_Op[((size_t)idx * QTOT + qq) * 32 + c];
            o4[0] += o.x; o4[1] += o.y; o4[2] += o.z; o4[3] += o.w;
        }
        float inv = 1.f / l;
        #pragma unroll
        for (int u = 0; u < 4; u++) {
            __nv_bfloat16 hi, lo;
            bf16_split(o4[u] * inv, hi, lo);
            AbfH[row * 136 + col0 + u] = hi;
            AbfL[row * 136 + col0 + u] = lo;
        }
    }
    __syncthreads();

    const int col = 16 * w + qn;

    // ---- GEMM1: Z = A @ Wp + bp + skip ----
    {
        float cA[4], cB[4];
        cA[0] = cA[2] = bp[col];     cA[1] = cA[3] = bp[col + 1];
        cB[0] = cB[2] = bp[col + 8]; cB[1] = cB[3] = bp[col + 9];
        hgemm16c(g_We, g_We + 81920, 128, 0, 0, AbfH, AbfL, WsH, WsL,
                 cA, cB, w, r, qn, tid);
        const float* sk = skip + (size_t)b * 128 * 1024 + p0;
        Zsf[r * 132 + col]           = cA[0] + sk[(size_t)col * 1024 + r];
        Zsf[r * 132 + col + 1]       = cA[1] + sk[(size_t)(col + 1) * 1024 + r];
        Zsf[(r + 8) * 132 + col]     = cA[2] + sk[(size_t)col * 1024 + r + 8];
        Zsf[(r + 8) * 132 + col + 1] = cA[3] + sk[(size_t)(col + 1) * 1024 + r + 8];
        Zsf[r * 132 + col + 8]       = cB[0] + sk[(size_t)(col + 8) * 1024 + r];
        Zsf[r * 132 + col + 9]       = cB[1] + sk[(size_t)(col + 9) * 1024 + r];
        Zsf[(r + 8) * 132 + col + 8] = cB[2] + sk[(size_t)(col + 8) * 1024 + r + 8];
        Zsf[(r + 8) * 132 + col + 9] = cB[3] + sk[(size_t)(col + 9) * 1024 + r + 8];
    }
    __syncthreads();

    // ---- pre-LN -> Zsf (fp32) and A hi/lo (GEMM2 input) ----
    {
        const int r2 = tid >> 4, sl = tid & 15;
        float sum = 0.f;
        #pragma unroll
        for (int t = 0; t < 8; t++) sum += Zsf[r2 * 132 + sl + 16 * t];
        sum += __shfl_xor_sync(~0u, sum, 1); sum += __shfl_xor_sync(~0u, sum, 2);
        sum += __shfl_xor_sync(~0u, sum, 4); sum += __shfl_xor_sync(~0u, sum, 8);
        const float mu = sum * (1.f / 128.f);
        float v = 0.f;
        #pragma unroll
        for (int t = 0; t < 8; t++) { float d = Zsf[r2 * 132 + sl + 16 * t] - mu; v += d * d; }
        v += __shfl_xor_sync(~0u, v, 1); v += __shfl_xor_sync(~0u, v, 2);
        v += __shfl_xor_sync(~0u, v, 4); v += __shfl_xor_sync(~0u, v, 8);
        const float rstd = rsqrtf(v * (1.f / 128.f) + 1e-5f);
        #pragma unroll
        for (int t = 0; t < 8; t++) {
            int d = sl + 16 * t;
            float val = (Zsf[r2 * 132 + d] - mu) * rstd * pre_g[d] + pre_b[d];
            Zsf[r2 * 132 + d] = val;
            __nv_bfloat16 hi, lo;
            bf16_split(val, hi, lo);
            AbfH[r2 * 136 + d] = hi;
            AbfL[r2 * 136 + d] = lo;
        }
    }
    __syncthreads();

    // ---- MLP: GEMM2 (n-halves) + gelu + GEMM3 (k-halves) ----
    float o0[4], o1[4];
    o0[0] = o0[2] = b2[col];     o0[1] = o0[3] = b2[col + 1];
    o1[0] = o1[2] = b2[col + 8]; o1[1] = o1[3] = b2[col + 9];

    #pragma unroll 1
    for (int h = 0; h < 2; h++) {
        float hA[4], hB[4];
        const int hc = h * 128 + col;
        hA[0] = hA[2] = b1[hc];     hA[1] = hA[3] = b1[hc + 1];
        hB[0] = hB[2] = b1[hc + 8]; hB[1] = hB[3] = b1[hc + 9];
        hgemm16c(g_We + 16384, g_We + 81920 + 16384, 128, h * 128, 0,
                 AbfH, AbfL, WsH, WsL, hA, hB, w, r, qn, tid);
        #pragma unroll
        for (int u = 0; u < 4; u++) {
            hA[u] = 0.5f * hA[u] * (1.f + erff(hA[u] * 0.70710678118654752f));
            hB[u] = 0.5f * hB[u] * (1.f + erff(hB[u] * 0.70710678118654752f));
        }
        __nv_bfloat16 hi, lo;
        bf16_split(hA[0], hi, lo); HbfH[r * 136 + col] = hi;           HbfL[r * 136 + col] = lo;
        bf16_split(hA[1], hi, lo); HbfH[r * 136 + col + 1] = hi;       HbfL[r * 136 + col + 1] = lo;
        bf16_split(hA[2], hi, lo); HbfH[(r + 8) * 136 + col] = hi;     HbfL[(r + 8) * 136 + col] = lo;
        bf16_split(hA[3], hi, lo); HbfH[(r + 8) * 136 + col + 1] = hi; HbfL[(r + 8) * 136 + col + 1] = lo;
        bf16_split(hB[0], hi, lo); HbfH[r * 136 + col + 8] = hi;       HbfL[r * 136 + col + 8] = lo;
        bf16_split(hB[1], hi, lo); HbfH[r * 136 + col + 9] = hi;       HbfL[r * 136 + col + 9] = lo;
        bf16_split(hB[2], hi, lo); HbfH[(r + 8) * 136 + col + 8] = hi; HbfL[(r + 8) * 136 + col + 8] = lo;
        bf16_split(hB[3], hi, lo); HbfH[(r + 8) * 136 + col + 9] = hi; HbfL[(r + 8) * 136 + col + 9] = lo;
        __syncthreads();
        hgemm16c(g_We + 49152, g_We + 81920 + 49152, 256, 0, h * 128,
                 HbfH, HbfL, WsH, WsL, o0, o1, w, r, qn, tid);
    }

    // ---- z2 = z + o ----
    Zsf[r * 132 + col]           += o0[0];
    Zsf[r * 132 + col + 1]       += o0[1];
    Zsf[(r + 8) * 132 + col]     += o0[2];
    Zsf[(r + 8) * 132 + col + 1] += o0[3];
    Zsf[r * 132 + col + 8]       += o1[0];
    Zsf[r * 132 + col + 9]       += o1[1];
    Zsf[(r + 8) * 132 + col + 8] += o1[2];
    Zsf[(r + 8) * 132 + col + 9] += o1[3];
    __syncthreads();

    // ---- post-LN + transposed write ----
    {
        const int r2 = tid >> 4, sl = tid & 15;
        float sum = 0.f;
        #pragma unroll
        for (int t = 0; t < 8; t++) sum += Zsf[r2 * 132 + sl + 16 * t];
        sum += __shfl_xor_sync(~0u, sum, 1); sum += __shfl_xor_sync(~0u, sum, 2);
        sum += __shfl_xor_sync(~0u, sum, 4); sum += __shfl_xor_sync(~0u, sum, 8);
        const float mu = sum * (1.f / 128.f);
        float v = 0.f;
        #pragma unroll
        for (int t = 0; t < 8; t++) { float d = Zsf[r2 * 132 + sl + 16 * t] - mu; v += d * d; }
        v += __shfl_xor_sync(~0u, v, 1); v += __shfl_xor_sync(~0u, v, 2);
        v += __shfl_xor_sync(~0u, v, 4); v += __shfl_xor_sync(~0u, v, 8);
        const float rstd = rsqrtf(v * (1.f / 128.f) + 1e-5f);
        #pragma unroll
        for (int t = 0; t < 8; t++) {
            int d = sl + 16 * t;
            out[((size_t)b * 128 + d) * 1024 + p0 + r2] =
                (Zsf[r2 * 132 + d] - mu) * rstd * post_g[d] + post_b[d];
        }
    }
}

// ===========================================================================
extern "C" void kernel_launch(void* const* d_in, const int* in_sizes, int n_in,
                              void* d_out, int out_size)
{
    const float* q      = (const float*)d_in[0];
    const float* k      = (const float*)d_in[1];
    const float* v      = (const float*)d_in[2];
    const float* skip   = (const float*)d_in[3];
    const float* q_g    = (const float*)d_in[4];
    const float* q_b    = (const float*)d_in[5];
    const float* Wq     = (const float*)d_in[6];
    const float* bq     = (const float*)d_in[7];
    const float* k_g    = (const float*)d_in[8];
    const float* k_b    = (const float*)d_in[9];
    const float* Wk     = (const float*)d_in[10];
    const float* bk     = (const float*)d_in[11];
    const float* v_g    = (const float*)d_in[12];
    const float* v_b    = (const float*)d_in[13];
    const float* Wv     = (const float*)d_in[14];
    const float* bv     = (const float*)d_in[15];
    const float* Wp     = (const float*)d_in[16];
    const float* bp     = (const float*)d_in[17];
    const float* pre_g  = (const float*)d_in[18];
    const float* pre_b  = (const float*)d_in[19];
    const float* W1     = (const float*)d_in[20];
    const float* b1     = (const float*)d_in[21];
    const float* W2     = (const float*)d_in[22];
    const float* b2     = (const float*)d_in[23];
    const float* post_g = (const float*)d_in[24];
    const float* post_b = (const float*)d_in[25];
    float* out = (float*)d_out;

    prep_kernel<<<128, 256>>>(Wq, Wk, Wv, Wp, W1, W2);
    proj_mma<<<dim3(53, NCAM, 6), 256>>>(q, k, v, q_g, q_b, k_g, k_b,
                                         v_g, v_b, bq, bk, bv);
    attn_mma<<<dim3(8, 8, 6), 256>>>();
    epi_kernel<<<128, 256>>>(skip, bp, pre_g, pre_b,
                             b1, b2, post_g, post_b, out);
}